// round 13
// baseline (speedup 1.0000x reference)
#include <cuda_runtime.h>
#include <cstdint>

// Problem constants
constexpr int Bq = 8, Tq = 1024, Dq = 512, Hq = 8, KDq = 64;
constexpr int BT = Bq * Tq;          // 8192
constexpr long long NOUT = (long long)BT * Dq;              // 4,194,304
constexpr long long NATT = (long long)Bq * Hq * Tq * Tq;    // 67,108,864

// Scratch (device globals: allocation-free rule)
__device__ float g_qh[BT * Dq];
__device__ float g_kh[BT * Dq];
__device__ float g_vh[BT * Dq];
__device__ float g_at[BT * Dq];
__device__ float g_q2[Bq * Hq * Tq];
__device__ float g_k2[Bq * Hq * Tq];

__device__ __forceinline__ unsigned f2tf(float x) {
    unsigned r;
    asm("cvt.rna.tf32.f32 %0, %1;" : "=r"(r) : "f"(x));
    return r;
}
__device__ __forceinline__ unsigned fbits(float x) { return __float_as_uint(x); }

__device__ __forceinline__ void mma_m16n8k8(float c[4], const unsigned a[4], const unsigned b[2]) {
    asm volatile(
        "mma.sync.aligned.m16n8k8.row.col.f32.tf32.tf32.f32 "
        "{%0,%1,%2,%3}, {%4,%5,%6,%7}, {%8,%9}, {%0,%1,%2,%3};"
        : "+f"(c[0]), "+f"(c[1]), "+f"(c[2]), "+f"(c[3])
        : "r"(a[0]), "r"(a[1]), "r"(a[2]), "r"(a[3]), "r"(b[0]), "r"(b[1]));
}

// ---------------------------------------------------------------------------
// K=512 GEMM: C[8192,512] = A[8192,512] @ W[512,512]   (R9 configuration)
// ---------------------------------------------------------------------------
template <int SPLIT>
__global__ void __launch_bounds__(256) gemm_k512(
    const float* __restrict__ A, const float* __restrict__ W, float* __restrict__ C)
{
    __shared__ float Ah[128][36];
    __shared__ float Al[(SPLIT == 3) ? 128 : 1][36];
    __shared__ float Wh[32][72];
    __shared__ float Wl[(SPLIT == 3) ? 32 : 1][72];

    const int tid = threadIdx.x;
    const int lane = tid & 31, warp = tid >> 5;
    const int gid = lane >> 2, tig = lane & 3;
    const int wm = warp & 3, wn = warp >> 2;
    const int m0 = blockIdx.y * 128, n0 = blockIdx.x * 64;

    float acc[2][4][4] = {};

    for (int k0 = 0; k0 < 512; k0 += 32) {
#pragma unroll
        for (int i = 0; i < 4; i++) {
            int idx = tid + i * 256;        // 1024 float4 for A 128x32
            int r = idx >> 3, c = (idx & 7) << 2;
            const float4 v = *reinterpret_cast<const float4*>(A + (size_t)(m0 + r) * 512 + k0 + c);
            if (SPLIT == 3) {
                float h0 = __uint_as_float(f2tf(v.x)), h1 = __uint_as_float(f2tf(v.y));
                float h2 = __uint_as_float(f2tf(v.z)), h3 = __uint_as_float(f2tf(v.w));
                Ah[r][c] = h0; Ah[r][c + 1] = h1; Ah[r][c + 2] = h2; Ah[r][c + 3] = h3;
                Al[r][c] = v.x - h0; Al[r][c + 1] = v.y - h1;
                Al[r][c + 2] = v.z - h2; Al[r][c + 3] = v.w - h3;
            } else {
                Ah[r][c] = v.x; Ah[r][c + 1] = v.y; Ah[r][c + 2] = v.z; Ah[r][c + 3] = v.w;
            }
        }
#pragma unroll
        for (int i = 0; i < 2; i++) {
            int idx = tid + i * 256;        // 512 float4 for W 32x64
            int r = idx >> 4, c = (idx & 15) << 2;
            const float4 v = *reinterpret_cast<const float4*>(W + (size_t)(k0 + r) * 512 + n0 + c);
            if (SPLIT == 3) {
                float h0 = __uint_as_float(f2tf(v.x)), h1 = __uint_as_float(f2tf(v.y));
                float h2 = __uint_as_float(f2tf(v.z)), h3 = __uint_as_float(f2tf(v.w));
                Wh[r][c] = h0; Wh[r][c + 1] = h1; Wh[r][c + 2] = h2; Wh[r][c + 3] = h3;
                Wl[r][c] = v.x - h0; Wl[r][c + 1] = v.y - h1;
                Wl[r][c + 2] = v.z - h2; Wl[r][c + 3] = v.w - h3;
            } else {
                Wh[r][c] = v.x; Wh[r][c + 1] = v.y; Wh[r][c + 2] = v.z; Wh[r][c + 3] = v.w;
            }
        }
        __syncthreads();

#pragma unroll
        for (int s = 0; s < 4; s++) {
            const int kk = s * 8;
            unsigned ah[2][4], al[2][4];
#pragma unroll
            for (int mi = 0; mi < 2; mi++) {
                const int r0 = wm * 32 + mi * 16;
                ah[mi][0] = fbits(Ah[r0 + gid][kk + tig]);
                ah[mi][1] = fbits(Ah[r0 + gid + 8][kk + tig]);
                ah[mi][2] = fbits(Ah[r0 + gid][kk + tig + 4]);
                ah[mi][3] = fbits(Ah[r0 + gid + 8][kk + tig + 4]);
                if (SPLIT == 3) {
                    al[mi][0] = fbits(Al[r0 + gid][kk + tig]);
                    al[mi][1] = fbits(Al[r0 + gid + 8][kk + tig]);
                    al[mi][2] = fbits(Al[r0 + gid][kk + tig + 4]);
                    al[mi][3] = fbits(Al[r0 + gid + 8][kk + tig + 4]);
                }
            }
            unsigned bh[4][2], bl[4][2];
#pragma unroll
            for (int ni = 0; ni < 4; ni++) {
                const int c0 = wn * 32 + ni * 8 + gid;
                bh[ni][0] = fbits(Wh[kk + tig][c0]);
                bh[ni][1] = fbits(Wh[kk + tig + 4][c0]);
                if (SPLIT == 3) {
                    bl[ni][0] = fbits(Wl[kk + tig][c0]);
                    bl[ni][1] = fbits(Wl[kk + tig + 4][c0]);
                }
            }
#pragma unroll
            for (int mi = 0; mi < 2; mi++)
#pragma unroll
                for (int ni = 0; ni < 4; ni++) {
                    if (SPLIT == 3) {
                        mma_m16n8k8(acc[mi][ni], al[mi], bh[ni]);
                        mma_m16n8k8(acc[mi][ni], ah[mi], bl[ni]);
                    }
                    mma_m16n8k8(acc[mi][ni], ah[mi], bh[ni]);
                }
        }
        __syncthreads();
    }

#pragma unroll
    for (int mi = 0; mi < 2; mi++)
#pragma unroll
        for (int ni = 0; ni < 4; ni++) {
            const int r = m0 + wm * 32 + mi * 16 + gid;
            const int c = n0 + wn * 32 + ni * 8 + tig * 2;
            *reinterpret_cast<float2*>(C + (size_t)r * 512 + c) =
                make_float2(acc[mi][ni][0], acc[mi][ni][1]);
            *reinterpret_cast<float2*>(C + (size_t)(r + 8) * 512 + c) =
                make_float2(acc[mi][ni][2], acc[mi][ni][3]);
        }
}

// ---------------------------------------------------------------------------
__global__ void norms_kernel()
{
    int idx = blockIdx.x * 256 + threadIdx.x;
    if (idx >= BT * Hq) return;
    int row = idx >> 3, h = idx & 7;
    const float* q = g_qh + (size_t)row * 512 + h * 64;
    const float* k = g_kh + (size_t)row * 512 + h * 64;
    float sq = 0.f, sk = 0.f;
#pragma unroll
    for (int i = 0; i < 16; i++) {
        float4 a = *reinterpret_cast<const float4*>(q + i * 4);
        sq += a.x * a.x + a.y * a.y + a.z * a.z + a.w * a.w;
        float4 c = *reinterpret_cast<const float4*>(k + i * 4);
        sk += c.x * c.x + c.y * c.y + c.z * c.z + c.w * c.w;
    }
    int b = row >> 10, t = row & 1023;
    g_q2[(size_t)(b * 8 + h) * 1024 + t] = sq;
    g_k2[(size_t)(b * 8 + h) * 1024 + t] = sk;
}

// ---------------------------------------------------------------------------
// Fused attention (mma.sync tf32) — R10 structure + DOUBLE-BUFFERED K/V:
//  - 128-row q tile, warp grid 4(m) x 2(n), warp tile 32x32
//  - permuted fragment-order smem (LDS.64) for Q hi/lo, K hi/lo, S; V row-major
//  - two K/V/k2 stages: stores for tile nt+1 issued at top of iter nt into the
//    idle stage, overlapping QK/exp/SV; 2 barriers per tile:
//      [A] sync; store stage[nxt]; QK(stage[cur]); exp->S+Sout; prefetch;
//      [B] sync; SV(stage[cur])
// smem = (2*128*72 + 128*72 + 2*3*64*72 + 256) floats = 222,208 B (1 CTA/SM)
// ---------------------------------------------------------------------------
constexpr int OQH  = 0;                     // Q hi  [128][72] permuted
constexpr int OQL  = OQH + 128 * 72;        // Q lo
constexpr int OSS  = OQL + 128 * 72;        // S     [128][72] permuted
constexpr int OBUF = OSS + 128 * 72;        // 2 stages
constexpr int SSTR = 3 * 64 * 72;           // stage stride: KH, KL, V
constexpr int OQ2  = OBUF + 2 * SSTR;       // q2 [128]
constexpr int OK2  = OQ2 + 128;             // k2 [2][64]
constexpr int ATTN_SMEM = (OK2 + 128) * 4;  // 222,208 bytes

__global__ void __launch_bounds__(256) attn_mma(float* __restrict__ Sout)
{
    extern __shared__ float sm[];
    const int tid = threadIdx.x, lane = tid & 31, warp = tid >> 5;
    const int gid = lane >> 2, tig = lane & 3;
    const int wm = warp & 3, wn = warp >> 2;
    const int bh = blockIdx.y, b = bh >> 3, h = bh & 7;
    const int m0 = blockIdx.x * 128;

    // --- Q tile load + hi/lo split into permuted layout (once) ---
    const float* qb = g_qh + ((size_t)(b * 1024 + m0)) * 512 + h * 64;
#pragma unroll
    for (int i = 0; i < 8; i++) {
        int idx = tid + i * 256;            // 2048 float4
        int r = idx >> 4, c = (idx & 15) << 2;
        float4 v = *reinterpret_cast<const float4*>(qb + (size_t)r * 512 + c);
        float h0 = __uint_as_float(f2tf(v.x)), h1 = __uint_as_float(f2tf(v.y));
        float h2 = __uint_as_float(f2tf(v.z)), h3 = __uint_as_float(f2tf(v.w));
        int base = r * 72 + (c & ~7) + ((c >> 2) & 1);   // +2 per successive col
        float* qh = sm + OQH + base;
        qh[0] = h0; qh[2] = h1; qh[4] = h2; qh[6] = h3;
        float* ql = sm + OQL + base;
        ql[0] = v.x - h0; ql[2] = v.y - h1; ql[4] = v.z - h2; ql[6] = v.w - h3;
    }
    if (tid < 128) sm[OQ2 + tid] = g_q2[(size_t)bh * 1024 + m0 + tid];

    const float* kb0 = g_kh + ((size_t)b * 1024) * 512 + h * 64;
    const float* vb0 = g_vh + ((size_t)b * 1024) * 512 + h * 64;

    // per-thread staging indices (constant across tiles)
    const int srr = tid >> 4, src = (tid & 15) << 2;       // idx base thread row/col
    const int sbase = srr * 72 + (src & ~7) + ((src >> 2) & 1);

    float4 kreg[4], vreg[4];
    float k2v = 0.f;

    // prefetch tile 0
#pragma unroll
    for (int i = 0; i < 4; i++) {
        int r = srr + i * 16;
        kreg[i] = *reinterpret_cast<const float4*>(kb0 + (size_t)r * 512 + src);
        vreg[i] = *reinterpret_cast<const float4*>(vb0 + (size_t)r * 512 + src);
    }
    if (tid < 64) k2v = g_k2[(size_t)bh * 1024 + tid];

    // store tile 0 -> stage 0 (no readers yet; visible after iter-0 [A])
    {
        float* KH = sm + OBUF;
        float* KL = KH + 64 * 72;
        float* VS = KL + 64 * 72;
#pragma unroll
        for (int i = 0; i < 4; i++) {
            float4 v = kreg[i];
            float h0 = __uint_as_float(f2tf(v.x)), h1 = __uint_as_float(f2tf(v.y));
            float h2 = __uint_as_float(f2tf(v.z)), h3 = __uint_as_float(f2tf(v.w));
            int bs = sbase + i * 16 * 72;
            KH[bs] = h0; KH[bs + 2] = h1; KH[bs + 4] = h2; KH[bs + 6] = h3;
            KL[bs] = v.x - h0; KL[bs + 2] = v.y - h1;
            KL[bs + 4] = v.z - h2; KL[bs + 6] = v.w - h3;
            *reinterpret_cast<float4*>(VS + (srr + i * 16) * 72 + src) = vreg[i];
        }
        if (tid < 64) sm[OK2 + tid] = k2v;
    }

    // prefetch tile 1
    if (true) {
#pragma unroll
        for (int i = 0; i < 4; i++) {
            int r = 64 + srr + i * 16;
            kreg[i] = *reinterpret_cast<const float4*>(kb0 + (size_t)r * 512 + src);
            vreg[i] = *reinterpret_cast<const float4*>(vb0 + (size_t)r * 512 + src);
        }
        if (tid < 64) k2v = g_k2[(size_t)bh * 1024 + 64 + tid];
    }

    float pacc[2][4][4] = {};

    for (int nt = 0; nt < 16; nt++) {
        const int cur = nt & 1, nxt = cur ^ 1;
        const int n0 = nt * 64;
        const int KHo = OBUF + cur * SSTR;
        const int VSo = KHo + 2 * 64 * 72;

        __syncthreads();   // [A] stage[cur] stores visible; stage[nxt] readers done

        // ---- store tile nt+1 -> stage[nxt] (overlaps all compute below) ----
        if (nt < 15) {
            float* KH = sm + OBUF + nxt * SSTR;
            float* KL = KH + 64 * 72;
            float* VS = KL + 64 * 72;
#pragma unroll
            for (int i = 0; i < 4; i++) {
                float4 v = kreg[i];
                float h0 = __uint_as_float(f2tf(v.x)), h1 = __uint_as_float(f2tf(v.y));
                float h2 = __uint_as_float(f2tf(v.z)), h3 = __uint_as_float(f2tf(v.w));
                int bs = sbase + i * 16 * 72;
                KH[bs] = h0; KH[bs + 2] = h1; KH[bs + 4] = h2; KH[bs + 6] = h3;
                KL[bs] = v.x - h0; KL[bs + 2] = v.y - h1;
                KL[bs + 4] = v.z - h2; KL[bs + 6] = v.w - h3;
                *reinterpret_cast<float4*>(VS + (srr + i * 16) * 72 + src) = vreg[i];
            }
            if (tid < 64) sm[OK2 + nxt * 64 + tid] = k2v;
        }

        // ---- QK^T: 3xTF32, wide LDS.64 + HMMA (stage[cur]) ----
        float sacc[2][4][4] = {};
#pragma unroll
        for (int s = 0; s < 8; s++) {
            const int so = s * 8 + tig * 2;
            unsigned ah[2][4], al[2][4];
#pragma unroll
            for (int mi = 0; mi < 2; mi++) {
                const float* ab = sm + OQH + (wm * 32 + mi * 16 + gid) * 72 + so;
                float2 u0 = *reinterpret_cast<const float2*>(ab);
                float2 u1 = *reinterpret_cast<const float2*>(ab + 8 * 72);
                ah[mi][0] = fbits(u0.x); ah[mi][1] = fbits(u1.x);
                ah[mi][2] = fbits(u0.y); ah[mi][3] = fbits(u1.y);
                const float* lb = ab + (OQL - OQH);
                float2 l0 = *reinterpret_cast<const float2*>(lb);
                float2 l1 = *reinterpret_cast<const float2*>(lb + 8 * 72);
                al[mi][0] = fbits(l0.x); al[mi][1] = fbits(l1.x);
                al[mi][2] = fbits(l0.y); al[mi][3] = fbits(l1.y);
            }
            unsigned bhf[4][2], blf[4][2];
#pragma unroll
            for (int ni = 0; ni < 4; ni++) {
                const float* kb = sm + KHo + (wn * 32 + ni * 8 + gid) * 72 + so;
                float2 w0 = *reinterpret_cast<const float2*>(kb);
                bhf[ni][0] = fbits(w0.x); bhf[ni][1] = fbits(w0.y);
                float2 w1 = *reinterpret_cast<const float2*>(kb + 64 * 72);
                blf[ni][0] = fbits(w1.x); blf[ni][1] = fbits(w1.y);
            }
#pragma unroll
            for (int mi = 0; mi < 2; mi++)
#pragma unroll
                for (int ni = 0; ni < 4; ni++) {
                    mma_m16n8k8(sacc[mi][ni], al[mi], bhf[ni]);
                    mma_m16n8k8(sacc[mi][ni], ah[mi], blf[ni]);
                    mma_m16n8k8(sacc[mi][ni], ah[mi], bhf[ni]);
                }
        }

        // ---- exp epilogue: S -> smem (permuted) + gmem (row-major) ----
#pragma unroll
        for (int mi = 0; mi < 2; mi++)
#pragma unroll
            for (int ni = 0; ni < 4; ni++) {
                const int r = wm * 32 + mi * 16 + gid;
                const int c = wn * 32 + ni * 8 + tig * 2;     // even
                float q2a = sm[OQ2 + r], q2b = sm[OQ2 + r + 8];
                float k2a = sm[OK2 + cur * 64 + c], k2b = sm[OK2 + cur * 64 + c + 1];
                float e00 = __expf(fmaf(2.f, sacc[mi][ni][0], -(q2a + k2a)));
                float e01 = __expf(fmaf(2.f, sacc[mi][ni][1], -(q2a + k2b)));
                float e10 = __expf(fmaf(2.f, sacc[mi][ni][2], -(q2b + k2a)));
                float e11 = __expf(fmaf(2.f, sacc[mi][ni][3], -(q2b + k2b)));
                const int cp = (c & ~7) + ((c & 3) << 1) + ((c >> 2) & 1);
                sm[OSS + r * 72 + cp] = e00;
                sm[OSS + r * 72 + cp + 2] = e01;
                sm[OSS + (r + 8) * 72 + cp] = e10;
                sm[OSS + (r + 8) * 72 + cp + 2] = e11;
                if (Sout) {
                    *reinterpret_cast<float2*>(
                        Sout + ((size_t)bh * 1024 + m0 + r) * 1024 + n0 + c) = make_float2(e00, e01);
                    *reinterpret_cast<float2*>(
                        Sout + ((size_t)bh * 1024 + m0 + r + 8) * 1024 + n0 + c) = make_float2(e10, e11);
                }
            }

        // ---- prefetch tile nt+2 (overlaps; regs free after top-of-loop store) ----
        if (nt < 14) {
            const int n2 = (nt + 2) * 64;
#pragma unroll
            for (int i = 0; i < 4; i++) {
                int r = n2 + srr + i * 16;
                kreg[i] = *reinterpret_cast<const float4*>(kb0 + (size_t)r * 512 + src);
                vreg[i] = *reinterpret_cast<const float4*>(vb0 + (size_t)r * 512 + src);
            }
            if (tid < 64) k2v = g_k2[(size_t)bh * 1024 + n2 + tid];
        }

        __syncthreads();   // [B] S fully written; stage[nxt] stores complete

        // ---- P += S @ V (S via LDS.64 permuted, V from stage[cur]) ----
#pragma unroll
        for (int s = 0; s < 8; s++) {
            const int so = s * 8 + tig * 2;
            const int kk = s * 8;
            unsigned af[2][4];
#pragma unroll
            for (int mi = 0; mi < 2; mi++) {
                const float* ab = sm + OSS + (wm * 32 + mi * 16 + gid) * 72 + so;
                float2 u0 = *reinterpret_cast<const float2*>(ab);
                float2 u1 = *reinterpret_cast<const float2*>(ab + 8 * 72);
                af[mi][0] = fbits(u0.x); af[mi][1] = fbits(u1.x);
                af[mi][2] = fbits(u0.y); af[mi][3] = fbits(u1.y);
            }
            unsigned bf[4][2];
#pragma unroll
            for (int ni = 0; ni < 4; ni++) {
                const int c0 = wn * 32 + ni * 8 + gid;
                bf[ni][0] = fbits(sm[VSo + (kk + tig) * 72 + c0]);
                bf[ni][1] = fbits(sm[VSo + (kk + tig + 4) * 72 + c0]);
            }
#pragma unroll
            for (int mi = 0; mi < 2; mi++)
#pragma unroll
                for (int ni = 0; ni < 4; ni++)
                    mma_m16n8k8(pacc[mi][ni], af[mi], bf[ni]);
        }
    }

    // ---- write P tile -> g_at [B*T, H*KD] ----
#pragma unroll
    for (int mi = 0; mi < 2; mi++)
#pragma unroll
        for (int ni = 0; ni < 4; ni++) {
            const int r = m0 + wm * 32 + mi * 16 + gid;
            const int c = h * 64 + wn * 32 + ni * 8 + tig * 2;
            float* dst = g_at + (size_t)(b * 1024 + r) * 512 + c;
            *reinterpret_cast<float2*>(dst) = make_float2(pacc[mi][ni][0], pacc[mi][ni][1]);
            *reinterpret_cast<float2*>(dst + (size_t)8 * 512) =
                make_float2(pacc[mi][ni][2], pacc[mi][ni][3]);
        }
}

// ---------------------------------------------------------------------------
extern "C" void kernel_launch(void* const* d_in, const int* in_sizes, int n_in,
                              void* d_out, int out_size)
{
    const float* query = (const float*)d_in[0];
    const float* key_  = (const float*)d_in[1];
    const float* value = (const float*)d_in[2];
    const float* Wq = (const float*)d_in[3];
    const float* Wk = (const float*)d_in[4];
    const float* Wv = (const float*)d_in[5];
    const float* Wo = (const float*)d_in[6];

    float *qh, *kh, *vh, *at;
    cudaGetSymbolAddress((void**)&qh, g_qh);
    cudaGetSymbolAddress((void**)&kh, g_kh);
    cudaGetSymbolAddress((void**)&vh, g_vh);
    cudaGetSymbolAddress((void**)&at, g_at);

    // Output layout: reference returns (out, attn_weights), flattened in order.
    float* outp = nullptr;
    float* attnW = nullptr;
    long long osz = (long long)out_size;
    if (osz >= NOUT + NATT) { outp = (float*)d_out; attnW = (float*)d_out + NOUT; }
    else if (osz >= NATT)   { attnW = (float*)d_out; }
    else                    { outp = (float*)d_out; }

    dim3 gg(8, 64);   // (N/64, M/128)  — exact R9 projection config
    gemm_k512<3><<<gg, 256>>>(query, Wq, qh);
    gemm_k512<3><<<gg, 256>>>(key_,  Wk, kh);
    gemm_k512<1><<<gg, 256>>>(value, Wv, vh);
    norms_kernel<<<(BT * Hq + 255) / 256, 256>>>();

    cudaFuncSetAttribute((const void*)attn_mma,
                         cudaFuncAttributeMaxDynamicSharedMemorySize, ATTN_SMEM);
    attn_mma<<<dim3(8, 64), 256, ATTN_SMEM>>>(attnW);

    if (outp) gemm_k512<1><<<gg, 256>>>(at, Wo, outp);
}

// round 15
// speedup vs baseline: 1.1063x; 1.1063x over previous
#include <cuda_runtime.h>
#include <cstdint>

// Problem constants
constexpr int Bq = 8, Tq = 1024, Dq = 512, Hq = 8, KDq = 64;
constexpr int BT = Bq * Tq;          // 8192
constexpr long long NOUT = (long long)BT * Dq;              // 4,194,304
constexpr long long NATT = (long long)Bq * Hq * Tq * Tq;    // 67,108,864

// Scratch (device globals: allocation-free rule)
__device__ float g_qh[BT * Dq];
__device__ float g_kh[BT * Dq];
__device__ float g_vh[BT * Dq];
__device__ float g_at[BT * Dq];
__device__ float g_at2[BT * Dq];
__device__ float g_q2[Bq * Hq * Tq];
__device__ float g_k2[Bq * Hq * Tq];

__device__ __forceinline__ unsigned f2tf(float x) {
    unsigned r;
    asm("cvt.rna.tf32.f32 %0, %1;" : "=r"(r) : "f"(x));
    return r;
}
__device__ __forceinline__ unsigned fbits(float x) { return __float_as_uint(x); }

__device__ __forceinline__ void mma_m16n8k8(float c[4], const unsigned a[4], const unsigned b[2]) {
    asm volatile(
        "mma.sync.aligned.m16n8k8.row.col.f32.tf32.tf32.f32 "
        "{%0,%1,%2,%3}, {%4,%5,%6,%7}, {%8,%9}, {%0,%1,%2,%3};"
        : "+f"(c[0]), "+f"(c[1]), "+f"(c[2]), "+f"(c[3])
        : "r"(a[0]), "r"(a[1]), "r"(a[2]), "r"(a[3]), "r"(b[0]), "r"(b[1]));
}

// ---------------------------------------------------------------------------
// K=512 GEMM: C[8192,512] = A[8192,512] @ W[512,512]
// SPLIT=3: 3xTF32 hi/lo staged in smem (cvt at store), occupancy 1 (regs).
// SPLIT=1: plain tf32; low reg demand -> MINB=2 for 2 CTAs/SM.
// ADD (compile-time): sums Aadd into A at load (out-GEMM only).
// ---------------------------------------------------------------------------
template <int SPLIT, bool ADD, int MINB>
__global__ void __launch_bounds__(256, MINB) gemm_k512(
    const float* __restrict__ A, const float* __restrict__ Aadd,
    const float* __restrict__ W, float* __restrict__ C)
{
    __shared__ float Ah[128][36];
    __shared__ float Al[(SPLIT == 3) ? 128 : 1][36];
    __shared__ float Wh[32][72];
    __shared__ float Wl[(SPLIT == 3) ? 32 : 1][72];

    const int tid = threadIdx.x;
    const int lane = tid & 31, warp = tid >> 5;
    const int gid = lane >> 2, tig = lane & 3;
    const int wm = warp & 3, wn = warp >> 2;
    const int m0 = blockIdx.y * 128, n0 = blockIdx.x * 64;

    float acc[2][4][4] = {};

    for (int k0 = 0; k0 < 512; k0 += 32) {
#pragma unroll
        for (int i = 0; i < 4; i++) {
            int idx = tid + i * 256;        // 1024 float4 for A 128x32
            int r = idx >> 3, c = (idx & 7) << 2;
            float4 v = *reinterpret_cast<const float4*>(A + (size_t)(m0 + r) * 512 + k0 + c);
            if (ADD) {
                const float4 w = *reinterpret_cast<const float4*>(
                    Aadd + (size_t)(m0 + r) * 512 + k0 + c);
                v.x += w.x; v.y += w.y; v.z += w.z; v.w += w.w;
            }
            if (SPLIT == 3) {
                float h0 = __uint_as_float(f2tf(v.x)), h1 = __uint_as_float(f2tf(v.y));
                float h2 = __uint_as_float(f2tf(v.z)), h3 = __uint_as_float(f2tf(v.w));
                Ah[r][c] = h0; Ah[r][c + 1] = h1; Ah[r][c + 2] = h2; Ah[r][c + 3] = h3;
                Al[r][c] = v.x - h0; Al[r][c + 1] = v.y - h1;
                Al[r][c + 2] = v.z - h2; Al[r][c + 3] = v.w - h3;
            } else {
                Ah[r][c] = v.x; Ah[r][c + 1] = v.y; Ah[r][c + 2] = v.z; Ah[r][c + 3] = v.w;
            }
        }
#pragma unroll
        for (int i = 0; i < 2; i++) {
            int idx = tid + i * 256;        // 512 float4 for W 32x64
            int r = idx >> 4, c = (idx & 15) << 2;
            const float4 v = *reinterpret_cast<const float4*>(W + (size_t)(k0 + r) * 512 + n0 + c);
            if (SPLIT == 3) {
                float h0 = __uint_as_float(f2tf(v.x)), h1 = __uint_as_float(f2tf(v.y));
                float h2 = __uint_as_float(f2tf(v.z)), h3 = __uint_as_float(f2tf(v.w));
                Wh[r][c] = h0; Wh[r][c + 1] = h1; Wh[r][c + 2] = h2; Wh[r][c + 3] = h3;
                Wl[r][c] = v.x - h0; Wl[r][c + 1] = v.y - h1;
                Wl[r][c + 2] = v.z - h2; Wl[r][c + 3] = v.w - h3;
            } else {
                Wh[r][c] = v.x; Wh[r][c + 1] = v.y; Wh[r][c + 2] = v.z; Wh[r][c + 3] = v.w;
            }
        }
        __syncthreads();

#pragma unroll
        for (int s = 0; s < 4; s++) {
            const int kk = s * 8;
            unsigned ah[2][4], al[2][4];
#pragma unroll
            for (int mi = 0; mi < 2; mi++) {
                const int r0 = wm * 32 + mi * 16;
                ah[mi][0] = fbits(Ah[r0 + gid][kk + tig]);
                ah[mi][1] = fbits(Ah[r0 + gid + 8][kk + tig]);
                ah[mi][2] = fbits(Ah[r0 + gid][kk + tig + 4]);
                ah[mi][3] = fbits(Ah[r0 + gid + 8][kk + tig + 4]);
                if (SPLIT == 3) {
                    al[mi][0] = fbits(Al[r0 + gid][kk + tig]);
                    al[mi][1] = fbits(Al[r0 + gid + 8][kk + tig]);
                    al[mi][2] = fbits(Al[r0 + gid][kk + tig + 4]);
                    al[mi][3] = fbits(Al[r0 + gid + 8][kk + tig + 4]);
                }
            }
            unsigned bh[4][2], bl[4][2];
#pragma unroll
            for (int ni = 0; ni < 4; ni++) {
                const int c0 = wn * 32 + ni * 8 + gid;
                bh[ni][0] = fbits(Wh[kk + tig][c0]);
                bh[ni][1] = fbits(Wh[kk + tig + 4][c0]);
                if (SPLIT == 3) {
                    bl[ni][0] = fbits(Wl[kk + tig][c0]);
                    bl[ni][1] = fbits(Wl[kk + tig + 4][c0]);
                }
            }
#pragma unroll
            for (int mi = 0; mi < 2; mi++)
#pragma unroll
                for (int ni = 0; ni < 4; ni++) {
                    if (SPLIT == 3) {
                        mma_m16n8k8(acc[mi][ni], al[mi], bh[ni]);
                        mma_m16n8k8(acc[mi][ni], ah[mi], bl[ni]);
                    }
                    mma_m16n8k8(acc[mi][ni], ah[mi], bh[ni]);
                }
        }
        __syncthreads();
    }

#pragma unroll
    for (int mi = 0; mi < 2; mi++)
#pragma unroll
        for (int ni = 0; ni < 4; ni++) {
            const int r = m0 + wm * 32 + mi * 16 + gid;
            const int c = n0 + wn * 32 + ni * 8 + tig * 2;
            *reinterpret_cast<float2*>(C + (size_t)r * 512 + c) =
                make_float2(acc[mi][ni][0], acc[mi][ni][1]);
            *reinterpret_cast<float2*>(C + (size_t)(r + 8) * 512 + c) =
                make_float2(acc[mi][ni][2], acc[mi][ni][3]);
        }
}

// ---------------------------------------------------------------------------
__global__ void norms_kernel()
{
    int idx = blockIdx.x * 256 + threadIdx.x;
    if (idx >= BT * Hq) return;
    int row = idx >> 3, h = idx & 7;
    const float* q = g_qh + (size_t)row * 512 + h * 64;
    const float* k = g_kh + (size_t)row * 512 + h * 64;
    float sq = 0.f, sk = 0.f;
#pragma unroll
    for (int i = 0; i < 16; i++) {
        float4 a = *reinterpret_cast<const float4*>(q + i * 4);
        sq += a.x * a.x + a.y * a.y + a.z * a.z + a.w * a.w;
        float4 c = *reinterpret_cast<const float4*>(k + i * 4);
        sk += c.x * c.x + c.y * c.y + c.z * c.z + c.w * c.w;
    }
    int b = row >> 10, t = row & 1023;
    g_q2[(size_t)(b * 8 + h) * 1024 + t] = sq;
    g_k2[(size_t)(b * 8 + h) * 1024 + t] = sk;
}

// ---------------------------------------------------------------------------
// Fused attention — EXACT R10 configuration (measured 264 us):
//  - 128-row q tile, warp grid 4(m) x 2(n), permuted fragment-order smem
//    (LDS.64) for Q hi/lo, K hi/lo, S; V row-major; 3 barriers/tile
//  - grid z=2 key-range split; partial P -> g_at / g_at2
// smem = (2*128*72 + 3*64*72 + 128*72 + 192) * 4 = 166,656 B
// ---------------------------------------------------------------------------
constexpr int OQH = 0;                    // Q hi   [128][72] permuted cols
constexpr int OQL = OQH + 128 * 72;       // Q lo
constexpr int OKH = OQL + 128 * 72;       // K hi   [64][72] permuted cols
constexpr int OKL = OKH + 64 * 72;        // K lo
constexpr int OVS = OKL + 64 * 72;        // V      [64][72] row-major
constexpr int OSS = OVS + 64 * 72;        // S      [128][72] permuted cols
constexpr int OQ2 = OSS + 128 * 72;       // q2     [128]
constexpr int OK2 = OQ2 + 128;            // k2     [64]
constexpr int ATTN_SMEM = (OK2 + 64) * 4; // 166,656 bytes

__global__ void __launch_bounds__(256) attn_mma(float* __restrict__ Sout)
{
    extern __shared__ float sm[];
    const int tid = threadIdx.x, lane = tid & 31, warp = tid >> 5;
    const int gid = lane >> 2, tig = lane & 3;
    const int wm = warp & 3, wn = warp >> 2;
    const int bh = blockIdx.y, b = bh >> 3, h = bh & 7;
    const int m0 = blockIdx.x * 128;
    const int z = blockIdx.z;                 // key-range half

    // --- Q tile load + hi/lo split into permuted layout (once) ---
    const float* qb = g_qh + ((size_t)(b * 1024 + m0)) * 512 + h * 64;
#pragma unroll
    for (int i = 0; i < 8; i++) {
        int idx = tid + i * 256;            // 2048 float4
        int r = idx >> 4, c = (idx & 15) << 2;     // c % 4 == 0
        float4 v = *reinterpret_cast<const float4*>(qb + (size_t)r * 512 + c);
        float h0 = __uint_as_float(f2tf(v.x)), h1 = __uint_as_float(f2tf(v.y));
        float h2 = __uint_as_float(f2tf(v.z)), h3 = __uint_as_float(f2tf(v.w));
        int base = r * 72 + (c & ~7) + ((c >> 2) & 1);   // +2 per successive col
        float* qh = sm + OQH + base;
        qh[0] = h0; qh[2] = h1; qh[4] = h2; qh[6] = h3;
        float* ql = sm + OQL + base;
        ql[0] = v.x - h0; ql[2] = v.y - h1; ql[4] = v.z - h2; ql[6] = v.w - h3;
    }
    if (tid < 128) sm[OQ2 + tid] = g_q2[(size_t)bh * 1024 + m0 + tid];

    const float* kb0 = g_kh + ((size_t)b * 1024) * 512 + h * 64;
    const float* vb0 = g_vh + ((size_t)b * 1024) * 512 + h * 64;

    // --- prefetch first key tile of this half into registers ---
    float4 kreg[4], vreg[4];
    float k2v = 0.f;
    {
        const int n0 = z * 8 * 64;
#pragma unroll
        for (int i = 0; i < 4; i++) {
            int idx = tid + i * 256;        // 1024 float4 each
            int r = idx >> 4, c = (idx & 15) << 2;
            kreg[i] = *reinterpret_cast<const float4*>(kb0 + (size_t)(n0 + r) * 512 + c);
            vreg[i] = *reinterpret_cast<const float4*>(vb0 + (size_t)(n0 + r) * 512 + c);
        }
        if (tid < 64) k2v = g_k2[(size_t)bh * 1024 + n0 + tid];
    }

    float pacc[2][4][4] = {};

    for (int nt = 0; nt < 8; nt++) {
        const int kt = z * 8 + nt;
        const int n0 = kt * 64;
        __syncthreads();   // prev iter's reads of K/V/S smem done

        // ---- store prefetched K (split, permuted) / V (raw rows) / k2 ----
#pragma unroll
        for (int i = 0; i < 4; i++) {
            int idx = tid + i * 256;
            int r = idx >> 4, c = (idx & 15) << 2;
            float4 v = kreg[i];
            float h0 = __uint_as_float(f2tf(v.x)), h1 = __uint_as_float(f2tf(v.y));
            float h2 = __uint_as_float(f2tf(v.z)), h3 = __uint_as_float(f2tf(v.w));
            int base = r * 72 + (c & ~7) + ((c >> 2) & 1);
            float* kh = sm + OKH + base;
            kh[0] = h0; kh[2] = h1; kh[4] = h2; kh[6] = h3;
            float* kl = sm + OKL + base;
            kl[0] = v.x - h0; kl[2] = v.y - h1; kl[4] = v.z - h2; kl[6] = v.w - h3;
            *reinterpret_cast<float4*>(sm + OVS + r * 72 + c) = vreg[i];
        }
        if (tid < 64) sm[OK2 + tid] = k2v;
        __syncthreads();

        // ---- prefetch next tile (overlaps QK/exp/SV below) ----
        if (nt < 7) {
            const int n1 = (kt + 1) * 64;
#pragma unroll
            for (int i = 0; i < 4; i++) {
                int idx = tid + i * 256;
                int r = idx >> 4, c = (idx & 15) << 2;
                kreg[i] = *reinterpret_cast<const float4*>(
                    kb0 + (size_t)(n1 + r) * 512 + c);
                vreg[i] = *reinterpret_cast<const float4*>(
                    vb0 + (size_t)(n1 + r) * 512 + c);
            }
            if (tid < 64) k2v = g_k2[(size_t)bh * 1024 + n1 + tid];
        }

        // ---- QK^T: 3xTF32, wide LDS.64 + HMMA ----
        float sacc[2][4][4] = {};
#pragma unroll
        for (int s = 0; s < 8; s++) {
            const int so = s * 8 + tig * 2;
            unsigned ah[2][4], al[2][4];
#pragma unroll
            for (int mi = 0; mi < 2; mi++) {
                const float* ab = sm + OQH + (wm * 32 + mi * 16 + gid) * 72 + so;
                float2 u0 = *reinterpret_cast<const float2*>(ab);
                float2 u1 = *reinterpret_cast<const float2*>(ab + 8 * 72);
                ah[mi][0] = fbits(u0.x); ah[mi][1] = fbits(u1.x);
                ah[mi][2] = fbits(u0.y); ah[mi][3] = fbits(u1.y);
                const float* lb = ab + (OQL - OQH);
                float2 l0 = *reinterpret_cast<const float2*>(lb);
                float2 l1 = *reinterpret_cast<const float2*>(lb + 8 * 72);
                al[mi][0] = fbits(l0.x); al[mi][1] = fbits(l1.x);
                al[mi][2] = fbits(l0.y); al[mi][3] = fbits(l1.y);
            }
            unsigned bhf[4][2], blf[4][2];
#pragma unroll
            for (int ni = 0; ni < 4; ni++) {
                const float* kb = sm + OKH + (wn * 32 + ni * 8 + gid) * 72 + so;
                float2 w0 = *reinterpret_cast<const float2*>(kb);
                bhf[ni][0] = fbits(w0.x); bhf[ni][1] = fbits(w0.y);
                float2 w1 = *reinterpret_cast<const float2*>(kb + (OKL - OKH));
                blf[ni][0] = fbits(w1.x); blf[ni][1] = fbits(w1.y);
            }
#pragma unroll
            for (int mi = 0; mi < 2; mi++)
#pragma unroll
                for (int ni = 0; ni < 4; ni++) {
                    mma_m16n8k8(sacc[mi][ni], al[mi], bhf[ni]);
                    mma_m16n8k8(sacc[mi][ni], ah[mi], blf[ni]);
                    mma_m16n8k8(sacc[mi][ni], ah[mi], bhf[ni]);
                }
        }

        // ---- exp epilogue: S -> smem (permuted) + gmem (row-major) ----
#pragma unroll
        for (int mi = 0; mi < 2; mi++)
#pragma unroll
            for (int ni = 0; ni < 4; ni++) {
                const int r = wm * 32 + mi * 16 + gid;
                const int c = wn * 32 + ni * 8 + tig * 2;     // even
                float q2a = sm[OQ2 + r], q2b = sm[OQ2 + r + 8];
                float k2a = sm[OK2 + c], k2b = sm[OK2 + c + 1];
                float e00 = __expf(fmaf(2.f, sacc[mi][ni][0], -(q2a + k2a)));
                float e01 = __expf(fmaf(2.f, sacc[mi][ni][1], -(q2a + k2b)));
                float e10 = __expf(fmaf(2.f, sacc[mi][ni][2], -(q2b + k2a)));
                float e11 = __expf(fmaf(2.f, sacc[mi][ni][3], -(q2b + k2b)));
                const int cp = (c & ~7) + ((c & 3) << 1) + ((c >> 2) & 1);
                sm[OSS + r * 72 + cp] = e00;
                sm[OSS + r * 72 + cp + 2] = e01;
                sm[OSS + (r + 8) * 72 + cp] = e10;
                sm[OSS + (r + 8) * 72 + cp + 2] = e11;
                if (Sout) {
                    *reinterpret_cast<float2*>(
                        Sout + ((size_t)bh * 1024 + m0 + r) * 1024 + n0 + c) = make_float2(e00, e01);
                    *reinterpret_cast<float2*>(
                        Sout + ((size_t)bh * 1024 + m0 + r + 8) * 1024 + n0 + c) = make_float2(e10, e11);
                }
            }
        __syncthreads();   // Ss fully written (cross-warp) before S@V

        // ---- P += S @ V (tf32; S via LDS.64 permuted, V scalar conflict-free) ----
#pragma unroll
        for (int s = 0; s < 8; s++) {
            const int so = s * 8 + tig * 2;
            const int kk = s * 8;
            unsigned af[2][4];
#pragma unroll
            for (int mi = 0; mi < 2; mi++) {
                const float* ab = sm + OSS + (wm * 32 + mi * 16 + gid) * 72 + so;
                float2 u0 = *reinterpret_cast<const float2*>(ab);
                float2 u1 = *reinterpret_cast<const float2*>(ab + 8 * 72);
                af[mi][0] = fbits(u0.x); af[mi][1] = fbits(u1.x);
                af[mi][2] = fbits(u0.y); af[mi][3] = fbits(u1.y);
            }
            unsigned bf[4][2];
#pragma unroll
            for (int ni = 0; ni < 4; ni++) {
                const int c0 = wn * 32 + ni * 8 + gid;
                bf[ni][0] = fbits(sm[OVS + (kk + tig) * 72 + c0]);
                bf[ni][1] = fbits(sm[OVS + (kk + tig + 4) * 72 + c0]);
            }
#pragma unroll
            for (int mi = 0; mi < 2; mi++)
#pragma unroll
                for (int ni = 0; ni < 4; ni++)
                    mma_m16n8k8(pacc[mi][ni], af[mi], bf[ni]);
        }
    }

    // ---- write partial P tile -> g_at / g_at2 [B*T, H*KD] ----
    float* Pd = z ? g_at2 : g_at;
#pragma unroll
    for (int mi = 0; mi < 2; mi++)
#pragma unroll
        for (int ni = 0; ni < 4; ni++) {
            const int r = m0 + wm * 32 + mi * 16 + gid;
            const int c = h * 64 + wn * 32 + ni * 8 + tig * 2;
            float* dst = Pd + (size_t)(b * 1024 + r) * 512 + c;
            *reinterpret_cast<float2*>(dst) = make_float2(pacc[mi][ni][0], pacc[mi][ni][1]);
            *reinterpret_cast<float2*>(dst + (size_t)8 * 512) =
                make_float2(pacc[mi][ni][2], pacc[mi][ni][3]);
        }
}

// ---------------------------------------------------------------------------
extern "C" void kernel_launch(void* const* d_in, const int* in_sizes, int n_in,
                              void* d_out, int out_size)
{
    const float* query = (const float*)d_in[0];
    const float* key_  = (const float*)d_in[1];
    const float* value = (const float*)d_in[2];
    const float* Wq = (const float*)d_in[3];
    const float* Wk = (const float*)d_in[4];
    const float* Wv = (const float*)d_in[5];
    const float* Wo = (const float*)d_in[6];

    float *qh, *kh, *vh, *at, *at2;
    cudaGetSymbolAddress((void**)&qh,  g_qh);
    cudaGetSymbolAddress((void**)&kh,  g_kh);
    cudaGetSymbolAddress((void**)&vh,  g_vh);
    cudaGetSymbolAddress((void**)&at,  g_at);
    cudaGetSymbolAddress((void**)&at2, g_at2);

    // Output layout: reference returns (out, attn_weights), flattened in order.
    float* outp = nullptr;
    float* attnW = nullptr;
    long long osz = (long long)out_size;
    if (osz >= NOUT + NATT) { outp = (float*)d_out; attnW = (float*)d_out + NOUT; }
    else if (osz >= NATT)   { attnW = (float*)d_out; }
    else                    { outp = (float*)d_out; }

    dim3 gg(8, 64);   // (N/64, M/128) — exact R9 projection config
    gemm_k512<3, false, 1><<<gg, 256>>>(query, nullptr, Wq, qh);
    gemm_k512<3, false, 1><<<gg, 256>>>(key_,  nullptr, Wk, kh);
    gemm_k512<1, false, 2><<<gg, 256>>>(value, nullptr, Wv, vh);
    norms_kernel<<<(BT * Hq + 255) / 256, 256>>>();

    cudaFuncSetAttribute((const void*)attn_mma,
                         cudaFuncAttributeMaxDynamicSharedMemorySize, ATTN_SMEM);
    attn_mma<<<dim3(8, 64, 2), 256, ATTN_SMEM>>>(attnW);

    if (outp) gemm_k512<1, true, 2><<<gg, 256>>>(at, at2, Wo, outp);
}

// round 16
// speedup vs baseline: 1.4024x; 1.2676x over previous
#include <cuda_runtime.h>
#include <cuda_bf16.h>
#include <cstdint>

// Problem constants
constexpr int Bq = 8, Tq = 1024, Dq = 512, Hq = 8, KDq = 64;
constexpr int BT = Bq * Tq;          // 8192
constexpr long long NOUT = (long long)BT * Dq;              // 4,194,304
constexpr long long NATT = (long long)Bq * Hq * Tq * Tq;    // 67,108,864

// Scratch (device globals: allocation-free rule)
__device__ float g_qh[BT * Dq];
__device__ float g_kh[BT * Dq];
__device__ float g_vh[BT * Dq];
__device__ float g_at[BT * Dq];
__device__ float g_at2[BT * Dq];
__device__ float g_q2[Bq * Hq * Tq];
__device__ float g_k2[Bq * Hq * Tq];

// ---- bf16 helpers -------------------------------------------------------
__device__ __forceinline__ unsigned pack2bf(float lo, float hi) {
    unsigned r;
    asm("cvt.rn.bf16x2.f32 %0, %1, %2;" : "=r"(r) : "f"(hi), "f"(lo));
    return r;   // low half = lo (even col), high half = hi (odd col)
}
__device__ __forceinline__ float bflo(unsigned u) { return __uint_as_float(u << 16); }
__device__ __forceinline__ float bfhi(unsigned u) { return __uint_as_float(u & 0xffff0000u); }
__device__ __forceinline__ int permp(int p) {   // pair-permutation: (p, p+4) adjacent
    return (p & ~7) + ((p & 3) << 1) + ((p >> 2) & 1);
}

__device__ __forceinline__ void mma_bf16(float c[4], const unsigned a[4], const unsigned b[2]) {
    asm volatile(
        "mma.sync.aligned.m16n8k16.row.col.f32.bf16.bf16.f32 "
        "{%0,%1,%2,%3}, {%4,%5,%6,%7}, {%8,%9}, {%0,%1,%2,%3};"
        : "+f"(c[0]), "+f"(c[1]), "+f"(c[2]), "+f"(c[3])
        : "r"(a[0]), "r"(a[1]), "r"(a[2]), "r"(a[3]), "r"(b[0]), "r"(b[1]));
}

// ---------------------------------------------------------------------------
// K=512 GEMM: C[8192,512] = A[8192,512] @ W[512,512]  — bf16 m16n8k16
// SPLIT=3: 3-term bf16 split (al*bh + ah*bl + ah*bh); SPLIT=1: plain bf16.
// Operands as bf16x2 pairs, pair-permuted; W staged transposed [n][k-pairs].
// Row stride 24 uint32 (24g mod 32 = {0,24,16,8} -> conflict-free LDS.64).
// ---------------------------------------------------------------------------
template <int SPLIT, bool ADD, int MINB>
__global__ void __launch_bounds__(256, MINB) gemm_bf(
    const float* __restrict__ A, const float* __restrict__ Aadd,
    const float* __restrict__ W, float* __restrict__ C)
{
    __shared__ unsigned Ah[128 * 24];
    __shared__ unsigned Al[(SPLIT == 3) ? 128 * 24 : 1];
    __shared__ unsigned Wh[64 * 24];
    __shared__ unsigned Wl[(SPLIT == 3) ? 64 * 24 : 1];

    const int tid = threadIdx.x;
    const int lane = tid & 31, warp = tid >> 5;
    const int gid = lane >> 2, tig = lane & 3;
    const int wm = warp & 3, wn = warp >> 2;
    const int m0 = blockIdx.y * 128, n0 = blockIdx.x * 64;

    float acc[2][4][4] = {};

    for (int k0 = 0; k0 < 512; k0 += 32) {
        // ---- stage A [128 x 32] as bf16 pairs (16 pairs/row) ----
#pragma unroll
        for (int i = 0; i < 4; i++) {
            int idx = tid + i * 256;            // 1024 float4
            int r = idx >> 3, c = (idx & 7) << 2;
            float4 v = *reinterpret_cast<const float4*>(A + (size_t)(m0 + r) * 512 + k0 + c);
            if (ADD) {
                const float4 w = *reinterpret_cast<const float4*>(
                    Aadd + (size_t)(m0 + r) * 512 + k0 + c);
                v.x += w.x; v.y += w.y; v.z += w.z; v.w += w.w;
            }
            unsigned h01 = pack2bf(v.x, v.y), h23 = pack2bf(v.z, v.w);
            int pp0 = permp(c >> 1), pp1 = permp((c >> 1) + 1);
            Ah[r * 24 + pp0] = h01; Ah[r * 24 + pp1] = h23;
            if (SPLIT == 3) {
                Al[r * 24 + pp0] = pack2bf(v.x - bflo(h01), v.y - bfhi(h01));
                Al[r * 24 + pp1] = pack2bf(v.z - bflo(h23), v.w - bfhi(h23));
            }
        }
        // ---- stage W transposed [64 n][16 k-pairs] ----
#pragma unroll
        for (int i = 0; i < 2; i++) {
            int item = tid + i * 256;           // 512 items x 4 scalars
            int n = item & 63, kg = item >> 6;  // kg in 0..7
            const float* wp = W + (size_t)(k0 + kg * 4) * 512 + n0 + n;
            float w0 = wp[0], w1 = wp[512], w2 = wp[1024], w3 = wp[1536];
            unsigned h01 = pack2bf(w0, w1), h23 = pack2bf(w2, w3);
            int pp0 = permp(kg * 2), pp1 = permp(kg * 2 + 1);
            Wh[n * 24 + pp0] = h01; Wh[n * 24 + pp1] = h23;
            if (SPLIT == 3) {
                Wl[n * 24 + pp0] = pack2bf(w0 - bflo(h01), w1 - bfhi(h01));
                Wl[n * 24 + pp1] = pack2bf(w2 - bflo(h23), w3 - bfhi(h23));
            }
        }
        __syncthreads();

#pragma unroll
        for (int s = 0; s < 2; s++) {           // two k16 steps per k-tile
            const int so = s * 8 + tig * 2;
            unsigned ah[2][4], al[2][4];
#pragma unroll
            for (int mi = 0; mi < 2; mi++) {
                const int row = wm * 32 + mi * 16 + gid;
                uint2 u0 = *reinterpret_cast<const uint2*>(Ah + row * 24 + so);
                uint2 u1 = *reinterpret_cast<const uint2*>(Ah + (row + 8) * 24 + so);
                ah[mi][0] = u0.x; ah[mi][1] = u1.x; ah[mi][2] = u0.y; ah[mi][3] = u1.y;
                if (SPLIT == 3) {
                    uint2 l0 = *reinterpret_cast<const uint2*>(Al + row * 24 + so);
                    uint2 l1 = *reinterpret_cast<const uint2*>(Al + (row + 8) * 24 + so);
                    al[mi][0] = l0.x; al[mi][1] = l1.x; al[mi][2] = l0.y; al[mi][3] = l1.y;
                }
            }
            unsigned bh[4][2], bl[4][2];
#pragma unroll
            for (int ni = 0; ni < 4; ni++) {
                const int n = wn * 32 + ni * 8 + gid;
                uint2 w = *reinterpret_cast<const uint2*>(Wh + n * 24 + so);
                bh[ni][0] = w.x; bh[ni][1] = w.y;
                if (SPLIT == 3) {
                    uint2 l = *reinterpret_cast<const uint2*>(Wl + n * 24 + so);
                    bl[ni][0] = l.x; bl[ni][1] = l.y;
                }
            }
#pragma unroll
            for (int mi = 0; mi < 2; mi++)
#pragma unroll
                for (int ni = 0; ni < 4; ni++) {
                    if (SPLIT == 3) {
                        mma_bf16(acc[mi][ni], al[mi], bh[ni]);
                        mma_bf16(acc[mi][ni], ah[mi], bl[ni]);
                    }
                    mma_bf16(acc[mi][ni], ah[mi], bh[ni]);
                }
        }
        __syncthreads();
    }

#pragma unroll
    for (int mi = 0; mi < 2; mi++)
#pragma unroll
        for (int ni = 0; ni < 4; ni++) {
            const int r = m0 + wm * 32 + mi * 16 + gid;
            const int c = n0 + wn * 32 + ni * 8 + tig * 2;
            *reinterpret_cast<float2*>(C + (size_t)r * 512 + c) =
                make_float2(acc[mi][ni][0], acc[mi][ni][1]);
            *reinterpret_cast<float2*>(C + (size_t)(r + 8) * 512 + c) =
                make_float2(acc[mi][ni][2], acc[mi][ni][3]);
        }
}

// ---------------------------------------------------------------------------
__global__ void norms_kernel()
{
    int idx = blockIdx.x * 256 + threadIdx.x;
    if (idx >= BT * Hq) return;
    int row = idx >> 3, h = idx & 7;
    const float* q = g_qh + (size_t)row * 512 + h * 64;
    const float* k = g_kh + (size_t)row * 512 + h * 64;
    float sq = 0.f, sk = 0.f;
#pragma unroll
    for (int i = 0; i < 16; i++) {
        float4 a = *reinterpret_cast<const float4*>(q + i * 4);
        sq += a.x * a.x + a.y * a.y + a.z * a.z + a.w * a.w;
        float4 c = *reinterpret_cast<const float4*>(k + i * 4);
        sk += c.x * c.x + c.y * c.y + c.z * c.z + c.w * c.w;
    }
    int b = row >> 10, t = row & 1023;
    g_q2[(size_t)(b * 8 + h) * 1024 + t] = sq;
    g_k2[(size_t)(b * 8 + h) * 1024 + t] = sk;
}

// ---------------------------------------------------------------------------
// Fused attention — R15 structure, bf16 m16n8k16 operands:
//  - Q hi/lo, K hi/lo as bf16x2 pairs, pair-permuted, stride 40 uint32
//  - V transposed [kd][key-pairs] bf16; S packed bf16 pairs for S@V
//  - QK^T: 3-term bf16 split; S@V single bf16; z=2 key-range split
// smem = (3*5120 + 3*2560 + 192) uint32 = 92,928 B
// ---------------------------------------------------------------------------
constexpr int OQH = 0;                     // Q hi  [128][40]
constexpr int OQL = OQH + 128 * 40;        // Q lo
constexpr int OKH = OQL + 128 * 40;        // K hi  [64][40]
constexpr int OKL = OKH + 64 * 40;         // K lo
constexpr int OVT = OKL + 64 * 40;         // V^T   [64 kd][40] (key pairs)
constexpr int OSS = OVT + 64 * 40;         // S     [128][40]
constexpr int OQ2 = OSS + 128 * 40;        // q2 [128] (float)
constexpr int OK2 = OQ2 + 128;             // k2 [64]  (float)
constexpr int ATTN_SMEM = (OK2 + 64) * 4;  // 92,928 bytes

__global__ void __launch_bounds__(256) attn_mma(float* __restrict__ Sout)
{
    extern __shared__ unsigned smu[];
    float* smf = reinterpret_cast<float*>(smu);
    const int tid = threadIdx.x, lane = tid & 31, warp = tid >> 5;
    const int gid = lane >> 2, tig = lane & 3;
    const int wm = warp & 3, wn = warp >> 2;
    const int bh = blockIdx.y, b = bh >> 3, h = bh & 7;
    const int m0 = blockIdx.x * 128;
    const int z = blockIdx.z;                 // key-range half

    // --- Q tile: load f32, split hi/lo bf16 pairs (once) ---
    const float* qb = g_qh + ((size_t)(b * 1024 + m0)) * 512 + h * 64;
#pragma unroll
    for (int i = 0; i < 8; i++) {
        int idx = tid + i * 256;            // 2048 float4
        int r = idx >> 4, c = (idx & 15) << 2;
        float4 v = *reinterpret_cast<const float4*>(qb + (size_t)r * 512 + c);
        unsigned h01 = pack2bf(v.x, v.y), h23 = pack2bf(v.z, v.w);
        int base = r * 40;
        int pp0 = permp(c >> 1), pp1 = permp((c >> 1) + 1);
        smu[OQH + base + pp0] = h01; smu[OQH + base + pp1] = h23;
        smu[OQL + base + pp0] = pack2bf(v.x - bflo(h01), v.y - bfhi(h01));
        smu[OQL + base + pp1] = pack2bf(v.z - bflo(h23), v.w - bfhi(h23));
    }
    if (tid < 128) smf[OQ2 + tid] = g_q2[(size_t)bh * 1024 + m0 + tid];

    const float* kb0 = g_kh + ((size_t)b * 1024) * 512 + h * 64;
    const float* vb0 = g_vh + ((size_t)b * 1024) * 512 + h * 64;

    // --- prefetch first key tile of this half ---
    float4 kreg[4];
    float vreg[4][4];
    float k2v = 0.f;
    {
        const int n0 = z * 8 * 64;
#pragma unroll
        for (int i = 0; i < 4; i++) {
            int idx = tid + i * 256;
            int r = idx >> 4, c = (idx & 15) << 2;
            kreg[i] = *reinterpret_cast<const float4*>(kb0 + (size_t)(n0 + r) * 512 + c);
            int item = tid + i * 256;
            int vkd = item & 63, vt0 = (item >> 6) << 2;
#pragma unroll
            for (int j = 0; j < 4; j++)
                vreg[i][j] = vb0[(size_t)(n0 + vt0 + j) * 512 + vkd];
        }
        if (tid < 64) k2v = g_k2[(size_t)bh * 1024 + n0 + tid];
    }

    float pacc[2][4][4] = {};

    for (int nt = 0; nt < 8; nt++) {
        const int kt = z * 8 + nt;
        const int n0 = kt * 64;
        __syncthreads();   // prev iter's reads of K/V/S smem done

        // ---- store K (split, pairs) / V^T (bf16 pairs of keys) / k2 ----
#pragma unroll
        for (int i = 0; i < 4; i++) {
            int idx = tid + i * 256;
            int r = idx >> 4, c = (idx & 15) << 2;
            float4 v = kreg[i];
            unsigned h01 = pack2bf(v.x, v.y), h23 = pack2bf(v.z, v.w);
            int base = r * 40;
            int pp0 = permp(c >> 1), pp1 = permp((c >> 1) + 1);
            smu[OKH + base + pp0] = h01; smu[OKH + base + pp1] = h23;
            smu[OKL + base + pp0] = pack2bf(v.x - bflo(h01), v.y - bfhi(h01));
            smu[OKL + base + pp1] = pack2bf(v.z - bflo(h23), v.w - bfhi(h23));
            int item = tid + i * 256;
            int vkd = item & 63, vt0 = (item >> 6) << 2;
            int pv = vt0 >> 1;          // even pair index
            smu[OVT + vkd * 40 + permp(pv)]     = pack2bf(vreg[i][0], vreg[i][1]);
            smu[OVT + vkd * 40 + permp(pv + 1)] = pack2bf(vreg[i][2], vreg[i][3]);
        }
        if (tid < 64) smf[OK2 + tid] = k2v;
        __syncthreads();

        // ---- prefetch next tile (overlaps QK/exp/SV below) ----
        if (nt < 7) {
            const int n1 = (kt + 1) * 64;
#pragma unroll
            for (int i = 0; i < 4; i++) {
                int idx = tid + i * 256;
                int r = idx >> 4, c = (idx & 15) << 2;
                kreg[i] = *reinterpret_cast<const float4*>(
                    kb0 + (size_t)(n1 + r) * 512 + c);
                int item = tid + i * 256;
                int vkd = item & 63, vt0 = (item >> 6) << 2;
#pragma unroll
                for (int j = 0; j < 4; j++)
                    vreg[i][j] = vb0[(size_t)(n1 + vt0 + j) * 512 + vkd];
            }
            if (tid < 64) k2v = g_k2[(size_t)bh * 1024 + n1 + tid];
        }

        // ---- QK^T: 3-term bf16 split, 4 k16 steps ----
        float sacc[2][4][4] = {};
#pragma unroll
        for (int s = 0; s < 4; s++) {
            const int so = s * 8 + tig * 2;
            unsigned ah[2][4], al[2][4];
#pragma unroll
            for (int mi = 0; mi < 2; mi++) {
                const int row = wm * 32 + mi * 16 + gid;
                uint2 u0 = *reinterpret_cast<const uint2*>(smu + OQH + row * 40 + so);
                uint2 u1 = *reinterpret_cast<const uint2*>(smu + OQH + (row + 8) * 40 + so);
                ah[mi][0] = u0.x; ah[mi][1] = u1.x; ah[mi][2] = u0.y; ah[mi][3] = u1.y;
                uint2 l0 = *reinterpret_cast<const uint2*>(smu + OQL + row * 40 + so);
                uint2 l1 = *reinterpret_cast<const uint2*>(smu + OQL + (row + 8) * 40 + so);
                al[mi][0] = l0.x; al[mi][1] = l1.x; al[mi][2] = l0.y; al[mi][3] = l1.y;
            }
            unsigned bhf[4][2], blf[4][2];
#pragma unroll
            for (int ni = 0; ni < 4; ni++) {
                const int key = wn * 32 + ni * 8 + gid;
                uint2 w = *reinterpret_cast<const uint2*>(smu + OKH + key * 40 + so);
                bhf[ni][0] = w.x; bhf[ni][1] = w.y;
                uint2 l = *reinterpret_cast<const uint2*>(smu + OKL + key * 40 + so);
                blf[ni][0] = l.x; blf[ni][1] = l.y;
            }
#pragma unroll
            for (int mi = 0; mi < 2; mi++)
#pragma unroll
                for (int ni = 0; ni < 4; ni++) {
                    mma_bf16(sacc[mi][ni], al[mi], bhf[ni]);
                    mma_bf16(sacc[mi][ni], ah[mi], blf[ni]);
                    mma_bf16(sacc[mi][ni], ah[mi], bhf[ni]);
                }
        }

        // ---- exp epilogue: S -> gmem (f32) + smem (bf16 pairs) ----
#pragma unroll
        for (int mi = 0; mi < 2; mi++)
#pragma unroll
            for (int ni = 0; ni < 4; ni++) {
                const int r = wm * 32 + mi * 16 + gid;
                const int c = wn * 32 + ni * 8 + tig * 2;     // even
                float q2a = smf[OQ2 + r], q2b = smf[OQ2 + r + 8];
                float k2a = smf[OK2 + c], k2b = smf[OK2 + c + 1];
                float e00 = __expf(fmaf(2.f, sacc[mi][ni][0], -(q2a + k2a)));
                float e01 = __expf(fmaf(2.f, sacc[mi][ni][1], -(q2a + k2b)));
                float e10 = __expf(fmaf(2.f, sacc[mi][ni][2], -(q2b + k2a)));
                float e11 = __expf(fmaf(2.f, sacc[mi][ni][3], -(q2b + k2b)));
                const int pp = permp(c >> 1);
                smu[OSS + r * 40 + pp] = pack2bf(e00, e01);
                smu[OSS + (r + 8) * 40 + pp] = pack2bf(e10, e11);
                if (Sout) {
                    *reinterpret_cast<float2*>(
                        Sout + ((size_t)bh * 1024 + m0 + r) * 1024 + n0 + c) = make_float2(e00, e01);
                    *reinterpret_cast<float2*>(
                        Sout + ((size_t)bh * 1024 + m0 + r + 8) * 1024 + n0 + c) = make_float2(e10, e11);
                }
            }
        __syncthreads();   // Ss fully written (cross-warp) before S@V

        // ---- P += S @ V (bf16; S pairs, V^T pairs) ----
#pragma unroll
        for (int s = 0; s < 4; s++) {
            const int so = s * 8 + tig * 2;
            unsigned af[2][4];
#pragma unroll
            for (int mi = 0; mi < 2; mi++) {
                const int row = wm * 32 + mi * 16 + gid;
                uint2 u0 = *reinterpret_cast<const uint2*>(smu + OSS + row * 40 + so);
                uint2 u1 = *reinterpret_cast<const uint2*>(smu + OSS + (row + 8) * 40 + so);
                af[mi][0] = u0.x; af[mi][1] = u1.x; af[mi][2] = u0.y; af[mi][3] = u1.y;
            }
            unsigned bf[4][2];
#pragma unroll
            for (int ni = 0; ni < 4; ni++) {
                const int kd = wn * 32 + ni * 8 + gid;
                uint2 w = *reinterpret_cast<const uint2*>(smu + OVT + kd * 40 + so);
                bf[ni][0] = w.x; bf[ni][1] = w.y;
            }
#pragma unroll
            for (int mi = 0; mi < 2; mi++)
#pragma unroll
                for (int ni = 0; ni < 4; ni++)
                    mma_bf16(pacc[mi][ni], af[mi], bf[ni]);
        }
    }

    // ---- write partial P tile -> g_at / g_at2 [B*T, H*KD] ----
    float* Pd = z ? g_at2 : g_at;
#pragma unroll
    for (int mi = 0; mi < 2; mi++)
#pragma unroll
        for (int ni = 0; ni < 4; ni++) {
            const int r = m0 + wm * 32 + mi * 16 + gid;
            const int c = h * 64 + wn * 32 + ni * 8 + tig * 2;
            float* dst = Pd + (size_t)(b * 1024 + r) * 512 + c;
            *reinterpret_cast<float2*>(dst) = make_float2(pacc[mi][ni][0], pacc[mi][ni][1]);
            *reinterpret_cast<float2*>(dst + (size_t)8 * 512) =
                make_float2(pacc[mi][ni][2], pacc[mi][ni][3]);
        }
}

// ---------------------------------------------------------------------------
extern "C" void kernel_launch(void* const* d_in, const int* in_sizes, int n_in,
                              void* d_out, int out_size)
{
    const float* query = (const float*)d_in[0];
    const float* key_  = (const float*)d_in[1];
    const float* value = (const float*)d_in[2];
    const float* Wq = (const float*)d_in[3];
    const float* Wk = (const float*)d_in[4];
    const float* Wv = (const float*)d_in[5];
    const float* Wo = (const float*)d_in[6];

    float *qh, *kh, *vh, *at, *at2;
    cudaGetSymbolAddress((void**)&qh,  g_qh);
    cudaGetSymbolAddress((void**)&kh,  g_kh);
    cudaGetSymbolAddress((void**)&vh,  g_vh);
    cudaGetSymbolAddress((void**)&at,  g_at);
    cudaGetSymbolAddress((void**)&at2, g_at2);

    // Output layout: reference returns (out, attn_weights), flattened in order.
    float* outp = nullptr;
    float* attnW = nullptr;
    long long osz = (long long)out_size;
    if (osz >= NOUT + NATT) { outp = (float*)d_out; attnW = (float*)d_out + NOUT; }
    else if (osz >= NATT)   { attnW = (float*)d_out; }
    else                    { outp = (float*)d_out; }

    dim3 gg(8, 64);   // (N/64, M/128)
    gemm_bf<3, false, 1><<<gg, 256>>>(query, nullptr, Wq, qh);
    gemm_bf<3, false, 1><<<gg, 256>>>(key_,  nullptr, Wk, kh);
    gemm_bf<1, false, 2><<<gg, 256>>>(value, nullptr, Wv, vh);
    norms_kernel<<<(BT * Hq + 255) / 256, 256>>>();

    cudaFuncSetAttribute((const void*)attn_mma,
                         cudaFuncAttributeMaxDynamicSharedMemorySize, ATTN_SMEM);
    attn_mma<<<dim3(8, 64, 2), 256, ATTN_SMEM>>>(attnW);

    if (outp) gemm_bf<1, true, 2><<<gg, 256>>>(at, at2, Wo, outp);
}